// round 4
// baseline (speedup 1.0000x reference)
#include <cuda_runtime.h>
#include <cuda_bf16.h>

// Problem constants (fixed by setup_inputs)
#define RR   8
#define BB   8
#define LL   2048
#define PP   16384
#define HQ   32
#define HKV  8
#define GG   4
#define DK   128
#define DV   128
#define NWARPS 8
#define CC   4                  // token chunks per (r,b,h) for load balance
#define CHUNK (LL / CC)         // 512 tokens per chunk
#define RC   (RR * CC)          // 32 partials per (b,h)
#define KVSTRIDE (HKV * DK)     // floats per page row
#define SCALE 0.08838834764831845f
#define NEGV  -1e30f
#define FULL 0xffffffffu

// Scratch (allocation-free rule: __device__ globals)
__device__ float g_O[RC * BB * HKV * GG * DV];    // normalized partial outputs (4 MB)
__device__ float g_lse[RC * BB * HQ];             // per-partial lse

__global__ __launch_bounds__(256) void spgqa_decode_kernel(
    const float* __restrict__ q,
    const float* __restrict__ k_cache,
    const float* __restrict__ v_cache,
    const int*   __restrict__ kv_lens,
    const int*   __restrict__ btab)
{
    const int h    = blockIdx.x;          // kv head
    const int b    = blockIdx.y;          // batch
    const int rc   = blockIdx.z;          // split*CC + chunk
    const int r    = rc >> 2;
    const int c    = rc & 3;
    const int tid  = threadIdx.x;
    const int warp = tid >> 5;
    const int lane = tid & 31;

    int len = kv_lens[r * BB + b];
    if (len > LL) len = LL;
    if (len < 0)  len = 0;
    const int lo = c * CHUNK;
    const int hi = min(len, lo + CHUNK);

    // Q fragment: lane holds dims [4*lane, 4*lane+4) for each of G query heads,
    // pre-scaled so the dot is already the score.
    float4 qf[GG];
#pragma unroll
    for (int g = 0; g < GG; g++) {
        float4 t = *(const float4*)&q[((size_t)b * HQ + (size_t)h * GG + g) * DK + lane * 4];
        t.x *= SCALE; t.y *= SCALE; t.z *= SCALE; t.w *= SCALE;
        qf[g] = t;
    }

    const int*   bt    = btab + ((size_t)r * BB + b) * LL;
    const float* kbase = k_cache + ((size_t)r * PP) * KVSTRIDE + (size_t)h * DK + lane * 4;
    const float* vbase = v_cache + ((size_t)r * PP) * KVSTRIDE + (size_t)h * DK + lane * 4;

    // Per-lane softmax state for head (lane&3), replicated across 8 lane-groups.
    float m = NEGV, s = 0.f;
    float4 acc[GG];
#pragma unroll
    for (int g = 0; g < GG; g++) acc[g] = make_float4(0.f, 0.f, 0.f, 0.f);

    const bool fold0 = (lane & 1);
    const bool fold1 = (lane & 2);
    const int  lbase = lane & ~3;

    // ---- depth-2 software pipeline: tokens l, l+N in flight while computing ----
    float4 kbuf[2], vbuf[2];
#pragma unroll
    for (int i = 0; i < 2; i++) {
        const int li = lo + warp + i * NWARPS;
        if (li < hi) {
            const size_t poff = (size_t)bt[li] * KVSTRIDE;
            kbuf[i] = __ldcs((const float4*)(kbase + poff));
            vbuf[i] = __ldcs((const float4*)(vbase + poff));
        }
    }
    // page index for the next prefetch target (token l+2N), hoisted one iter ahead
    int nextpage = 0;
    {
        const int lp = lo + warp + 2 * NWARPS;
        if (lp < hi) nextpage = bt[lp];
    }

    int slot = 0;
    for (int l = lo + warp; l < hi; l += NWARPS, slot ^= 1) {
        const float4 k4 = kbuf[slot];
        const float4 v4 = vbuf[slot];

        // Prefetch token l+2N into the slot just freed; hoist bt for l+3N.
        const int lp = l + 2 * NWARPS;
        if (lp < hi) {
            const size_t poff = (size_t)nextpage * KVSTRIDE;
            kbuf[slot] = __ldcs((const float4*)(kbase + poff));
            vbuf[slot] = __ldcs((const float4*)(vbase + poff));
            const int lq = lp + NWARPS;
            if (lq < hi) nextpage = bt[lq];
        }

        // 4 partial dots (this lane's 4 dims), pre-scaled via qf.
        float d0 = qf[0].x * k4.x + qf[0].y * k4.y + qf[0].z * k4.z + qf[0].w * k4.w;
        float d1 = qf[1].x * k4.x + qf[1].y * k4.y + qf[1].z * k4.z + qf[1].w * k4.w;
        float d2 = qf[2].x * k4.x + qf[2].y * k4.y + qf[2].z * k4.z + qf[2].w * k4.w;
        float d3 = qf[3].x * k4.x + qf[3].y * k4.y + qf[3].z * k4.z + qf[3].w * k4.w;

        // Fold-reduce: 6 shfls give every lane the FULL dot for head (lane&3).
        float fa = (fold0 ? d1 : d0) + __shfl_xor_sync(FULL, fold0 ? d0 : d1, 1);
        float fb = (fold0 ? d3 : d2) + __shfl_xor_sync(FULL, fold0 ? d2 : d3, 1);
        float sc = (fold1 ? fb : fa) + __shfl_xor_sync(FULL, fold1 ? fa : fb, 2);
        sc += __shfl_xor_sync(FULL, sc, 4);
        sc += __shfl_xor_sync(FULL, sc, 8);
        sc += __shfl_xor_sync(FULL, sc, 16);

        // Warp-consistent check: did any head's running max move?
        const unsigned upd = __ballot_sync(FULL, sc > m);
        if (upd == 0u) {
            // Fast path (common after warm-up): no rescale needed.
            const float p = __expf(sc - m);
            s += p;
            const float p0 = __shfl_sync(FULL, p, lbase + 0);
            const float p1 = __shfl_sync(FULL, p, lbase + 1);
            const float p2 = __shfl_sync(FULL, p, lbase + 2);
            const float p3 = __shfl_sync(FULL, p, lbase + 3);
            acc[0].x += p0 * v4.x; acc[0].y += p0 * v4.y; acc[0].z += p0 * v4.z; acc[0].w += p0 * v4.w;
            acc[1].x += p1 * v4.x; acc[1].y += p1 * v4.y; acc[1].z += p1 * v4.z; acc[1].w += p1 * v4.w;
            acc[2].x += p2 * v4.x; acc[2].y += p2 * v4.y; acc[2].z += p2 * v4.z; acc[2].w += p2 * v4.w;
            acc[3].x += p3 * v4.x; acc[3].y += p3 * v4.y; acc[3].z += p3 * v4.z; acc[3].w += p3 * v4.w;
        } else {
            const float nm = fmaxf(m, sc);
            const float cf = __expf(m - nm);
            const float p  = __expf(sc - nm);
            s = s * cf + p;
            m = nm;
            const float c0 = __shfl_sync(FULL, cf, lbase + 0);
            const float c1 = __shfl_sync(FULL, cf, lbase + 1);
            const float c2 = __shfl_sync(FULL, cf, lbase + 2);
            const float c3 = __shfl_sync(FULL, cf, lbase + 3);
            const float p0 = __shfl_sync(FULL, p,  lbase + 0);
            const float p1 = __shfl_sync(FULL, p,  lbase + 1);
            const float p2 = __shfl_sync(FULL, p,  lbase + 2);
            const float p3 = __shfl_sync(FULL, p,  lbase + 3);
            acc[0].x = acc[0].x * c0 + p0 * v4.x; acc[0].y = acc[0].y * c0 + p0 * v4.y;
            acc[0].z = acc[0].z * c0 + p0 * v4.z; acc[0].w = acc[0].w * c0 + p0 * v4.w;
            acc[1].x = acc[1].x * c1 + p1 * v4.x; acc[1].y = acc[1].y * c1 + p1 * v4.y;
            acc[1].z = acc[1].z * c1 + p1 * v4.z; acc[1].w = acc[1].w * c1 + p1 * v4.w;
            acc[2].x = acc[2].x * c2 + p2 * v4.x; acc[2].y = acc[2].y * c2 + p2 * v4.y;
            acc[2].z = acc[2].z * c2 + p2 * v4.z; acc[2].w = acc[2].w * c2 + p2 * v4.w;
            acc[3].x = acc[3].x * c3 + p3 * v4.x; acc[3].y = acc[3].y * c3 + p3 * v4.y;
            acc[3].z = acc[3].z * c3 + p3 * v4.z; acc[3].w = acc[3].w * c3 + p3 * v4.w;
        }
    }

    // Cross-warp merge in shared memory
    __shared__ float sm[NWARPS][GG];
    __shared__ float ss[NWARPS][GG];
    __shared__ float sacc[NWARPS][GG][DV];

#pragma unroll
    for (int g = 0; g < GG; g++) {
        sacc[warp][g][lane * 4 + 0] = acc[g].x;
        sacc[warp][g][lane * 4 + 1] = acc[g].y;
        sacc[warp][g][lane * 4 + 2] = acc[g].z;
        sacc[warp][g][lane * 4 + 3] = acc[g].w;
    }
    if (lane < GG) { sm[warp][lane] = m; ss[warp][lane] = s; }  // lane&3==lane for lane<4
    __syncthreads();

    if (warp < GG) {
        const int g = warp;
        float M = NEGV;
#pragma unroll
        for (int w = 0; w < NWARPS; w++) M = fmaxf(M, sm[w][g]);

        float S = 0.f;
        float cw[NWARPS];
#pragma unroll
        for (int w = 0; w < NWARPS; w++) {
            cw[w] = __expf(sm[w][g] - M);
            S += ss[w][g] * cw[w];
        }

        float4 o = make_float4(0.f, 0.f, 0.f, 0.f);
#pragma unroll
        for (int w = 0; w < NWARPS; w++) {
            const float wc = cw[w];
            o.x += wc * sacc[w][g][lane * 4 + 0];
            o.y += wc * sacc[w][g][lane * 4 + 1];
            o.z += wc * sacc[w][g][lane * 4 + 2];
            o.w += wc * sacc[w][g][lane * 4 + 3];
        }

        const float Sc  = fmaxf(S, 1e-30f);
        const float inv = 1.0f / Sc;
        float* Od = &g_O[((((size_t)rc * BB + b) * HKV + h) * GG + g) * DV + lane * 4];
        Od[0] = o.x * inv; Od[1] = o.y * inv; Od[2] = o.z * inv; Od[3] = o.w * inv;

        if (lane == 0)
            g_lse[((size_t)rc * BB + b) * HQ + h * GG + g] = M + logf(Sc);
    }
}

// Flat combine over all RC=32 partials (softmax-merge associativity makes this
// equal to the reference's per-r-then-across-r two-stage combine, including
// the 1e-30 clamps and empty-split behavior).
__global__ __launch_bounds__(128) void spgqa_combine_kernel(float* __restrict__ out)
{
    const int bh = blockIdx.x;       // 0..B*HQ-1
    const int b  = bh / HQ;
    const int hq = bh % HQ;
    const int h  = hq / GG;
    const int g  = hq % GG;
    const int d  = threadIdx.x;      // 0..127

    __shared__ float slse[RC];
    if (threadIdx.x < RC)
        slse[threadIdx.x] = g_lse[((size_t)threadIdx.x * BB + b) * HQ + hq];
    __syncthreads();

    float gm = NEGV;
#pragma unroll
    for (int p = 0; p < RC; p++) gm = fmaxf(gm, slse[p]);

    float wsum = 0.f;
    float accv = 0.f;
#pragma unroll
    for (int p = 0; p < RC; p++) {
        const float w = __expf(slse[p] - gm);
        wsum += w;
        accv += w * g_O[((((size_t)p * BB + b) * HKV + h) * GG + g) * DV + d];
    }
    wsum = fmaxf(wsum, 1e-30f);

    out[((size_t)b * HQ + hq) * DV + d] = accv / wsum;
}

extern "C" void kernel_launch(void* const* d_in, const int* in_sizes, int n_in,
                              void* d_out, int out_size)
{
    const float* q        = (const float*)d_in[0];
    const float* k_cache  = (const float*)d_in[1];
    const float* v_cache  = (const float*)d_in[2];
    const int*   kv_lens  = (const int*)d_in[3];
    const int*   btab     = (const int*)d_in[4];
    float*       out      = (float*)d_out;

    dim3 grid1(HKV, BB, RC);
    spgqa_decode_kernel<<<grid1, 256>>>(q, k_cache, v_cache, kv_lens, btab);
    spgqa_combine_kernel<<<BB * HQ, 128>>>(out);
}